// round 2
// baseline (speedup 1.0000x reference)
#include <cuda_runtime.h>
#include <math.h>

#define N_TOK 4096
#define DIM   1024
#define HID   4096
#define NEXP  8

// ---------------- scratch (allocation-free: __device__ globals) ----------------
__device__ int   g_tok[NEXP][N_TOK];
__device__ float g_wgt[NEXP][N_TOK];
__device__ int   g_cnt[NEXP];
__device__ int   g_off[NEXP];
// top_k = 2 -> exactly 2*N_TOK (expert, token) assignments total
__device__ float g_h[(size_t)2 * N_TOK * HID];   // 134 MB

// ---------------- init: zero output + counters ----------------
__global__ void init_kernel(float* __restrict__ y, int out_size) {
    int tid = blockIdx.x * blockDim.x + threadIdx.x;
    if (tid < NEXP) g_cnt[tid] = 0;
    int stride = gridDim.x * blockDim.x;
    for (int i = tid; i < out_size; i += stride) y[i] = 0.f;
}

// ---------------- router: logits, top-2, softmax, scatter ----------------
__global__ void router_kernel(const float* __restrict__ x,
                              const float* __restrict__ gw,
                              const float* __restrict__ rs) {
    __shared__ float sgw[NEXP * DIM];  // 32 KB
    int tid = threadIdx.x;
    for (int i = tid; i < NEXP * DIM; i += blockDim.x) sgw[i] = gw[i];
    __syncthreads();

    int warp = tid >> 5, lane = tid & 31;
    int n = blockIdx.x * (blockDim.x >> 5) + warp;
    if (n >= N_TOK) return;

    const float* xr = x + (size_t)n * DIM;
    float acc[NEXP];
    #pragma unroll
    for (int e = 0; e < NEXP; e++) acc[e] = 0.f;

    for (int d = lane; d < DIM; d += 32) {
        float xv = xr[d];
        #pragma unroll
        for (int e = 0; e < NEXP; e++) acc[e] += xv * sgw[e * DIM + d];
    }
    #pragma unroll
    for (int off = 16; off > 0; off >>= 1) {
        #pragma unroll
        for (int e = 0; e < NEXP; e++)
            acc[e] += __shfl_down_sync(0xffffffffu, acc[e], off);
    }

    if (lane == 0) {
        float s = rs[0];
        float v[NEXP];
        #pragma unroll
        for (int e = 0; e < NEXP; e++) v[e] = acc[e] * s;

        // top-1 (ties -> lowest index, matching jax.lax.top_k)
        int i0 = 0; float v0 = v[0];
        #pragma unroll
        for (int e = 1; e < NEXP; e++) if (v[e] > v0) { v0 = v[e]; i0 = e; }
        // top-2
        int i1 = -1; float v1 = -INFINITY;
        #pragma unroll
        for (int e = 0; e < NEXP; e++)
            if (e != i0 && v[e] > v1) { v1 = v[e]; i1 = e; }

        // softmax over the two selected logits (v0 >= v1)
        float t = expf(v1 - v0);
        float w0 = 1.f / (1.f + t);
        float w1 = t / (1.f + t);

        int s0 = atomicAdd(&g_cnt[i0], 1);
        g_tok[i0][s0] = n; g_wgt[i0][s0] = w0;
        int s1 = atomicAdd(&g_cnt[i1], 1);
        g_tok[i1][s1] = n; g_wgt[i1][s1] = w1;
    }
}

// ---------------- tiny exclusive scan over 8 counts ----------------
__global__ void scan_kernel() {
    if (threadIdx.x == 0 && blockIdx.x == 0) {
        int acc = 0;
        #pragma unroll
        for (int e = 0; e < NEXP; e++) { g_off[e] = acc; acc += g_cnt[e]; }
    }
}

// ---------------- GEMM 1: h = silu(x@w1^T + b1) * (x@w2^T + b2), per-expert groups ----------------
// 128x128x8 tile, 256 threads, 8x8 microtile, dual-B accumulation.
__global__ __launch_bounds__(256, 1)
void gemm_h_kernel(const float* __restrict__ x,
                   const float* __restrict__ w1, const float* __restrict__ b1,
                   const float* __restrict__ w2, const float* __restrict__ b2) {
    const int e = blockIdx.z;
    const int cnt = g_cnt[e];
    const int row0 = blockIdx.y * 128;
    if (row0 >= cnt) return;
    const int col0 = blockIdx.x * 128;
    const int goff = g_off[e];

    __shared__ float As[8][128];
    __shared__ float B1s[8][128];
    __shared__ float B2s[8][128];

    const int tid = threadIdx.x;
    const int lr = tid >> 1;          // 0..127: row within tile (A) / col within tile (B)
    const int lk = (tid & 1) * 4;     // 0 or 4: k offset

    int arow = row0 + lr;
    if (arow >= cnt) arow = cnt - 1;  // clamp; masked at store
    const int atok = g_tok[e][arow];
    const float* ap  = x  + (size_t)atok * DIM + lk;
    const float* b1p = w1 + (size_t)e * HID * DIM + (size_t)(col0 + lr) * DIM + lk;
    const float* b2p = w2 + (size_t)e * HID * DIM + (size_t)(col0 + lr) * DIM + lk;

    const int tx = tid & 15, ty = tid >> 4;

    float acc1[8][8], acc2[8][8];
    #pragma unroll
    for (int i = 0; i < 8; i++)
        #pragma unroll
        for (int j = 0; j < 8; j++) { acc1[i][j] = 0.f; acc2[i][j] = 0.f; }

    float4 av  = *(const float4*)ap;
    float4 b1v = *(const float4*)b1p;
    float4 b2v = *(const float4*)b2p;

    for (int k0 = 0; k0 < DIM; k0 += 8) {
        As [lk+0][lr] = av.x;  As [lk+1][lr] = av.y;  As [lk+2][lr] = av.z;  As [lk+3][lr] = av.w;
        B1s[lk+0][lr] = b1v.x; B1s[lk+1][lr] = b1v.y; B1s[lk+2][lr] = b1v.z; B1s[lk+3][lr] = b1v.w;
        B2s[lk+0][lr] = b2v.x; B2s[lk+1][lr] = b2v.y; B2s[lk+2][lr] = b2v.z; B2s[lk+3][lr] = b2v.w;
        __syncthreads();

        if (k0 + 8 < DIM) {  // prefetch next K-tile into registers
            ap += 8; b1p += 8; b2p += 8;
            av = *(const float4*)ap; b1v = *(const float4*)b1p; b2v = *(const float4*)b2p;
        }

        #pragma unroll
        for (int k = 0; k < 8; k++) {
            float a[8], r1[8], r2[8];
            #pragma unroll
            for (int i = 0; i < 8; i++) a[i] = As[k][ty * 8 + i];
            #pragma unroll
            for (int j = 0; j < 8; j++) { r1[j] = B1s[k][tx * 8 + j]; r2[j] = B2s[k][tx * 8 + j]; }
            #pragma unroll
            for (int i = 0; i < 8; i++)
                #pragma unroll
                for (int j = 0; j < 8; j++) {
                    acc1[i][j] += a[i] * r1[j];
                    acc2[i][j] += a[i] * r2[j];
                }
        }
        __syncthreads();
    }

    // SwiGLU epilogue -> h scratch
    #pragma unroll
    for (int i = 0; i < 8; i++) {
        int r = row0 + ty * 8 + i;
        if (r < cnt) {
            float* hp = g_h + (size_t)(goff + r) * HID + col0 + tx * 8;
            #pragma unroll
            for (int j = 0; j < 8; j++) {
                int c = col0 + tx * 8 + j;
                float g1 = acc1[i][j] + b1[e * HID + c];
                float g2 = acc2[i][j] + b2[e * HID + c];
                float sig = 1.f / (1.f + __expf(-g1));
                hp[j] = g1 * sig * g2;
            }
        }
    }
}

// ---------------- GEMM 2: y += (h @ w3^T + b3) * combine_weight ----------------
__global__ __launch_bounds__(256, 1)
void gemm_o_kernel(const float* __restrict__ w3, const float* __restrict__ b3,
                   float* __restrict__ y) {
    const int e = blockIdx.z;
    const int cnt = g_cnt[e];
    const int row0 = blockIdx.y * 128;
    if (row0 >= cnt) return;
    const int col0 = blockIdx.x * 128;
    const int goff = g_off[e];

    __shared__ float As[8][128];
    __shared__ float Bs[8][128];

    const int tid = threadIdx.x;
    const int lr = tid >> 1;
    const int lk = (tid & 1) * 4;

    int arow = row0 + lr;
    if (arow >= cnt) arow = cnt - 1;
    const float* ap = g_h + (size_t)(goff + arow) * HID + lk;
    const float* bp = w3 + (size_t)e * DIM * HID + (size_t)(col0 + lr) * HID + lk;

    const int tx = tid & 15, ty = tid >> 4;

    float acc[8][8];
    #pragma unroll
    for (int i = 0; i < 8; i++)
        #pragma unroll
        for (int j = 0; j < 8; j++) acc[i][j] = 0.f;

    float4 av = *(const float4*)ap;
    float4 bv = *(const float4*)bp;

    for (int k0 = 0; k0 < HID; k0 += 8) {
        As[lk+0][lr] = av.x; As[lk+1][lr] = av.y; As[lk+2][lr] = av.z; As[lk+3][lr] = av.w;
        Bs[lk+0][lr] = bv.x; Bs[lk+1][lr] = bv.y; Bs[lk+2][lr] = bv.z; Bs[lk+3][lr] = bv.w;
        __syncthreads();

        if (k0 + 8 < HID) {
            ap += 8; bp += 8;
            av = *(const float4*)ap; bv = *(const float4*)bp;
        }

        #pragma unroll
        for (int k = 0; k < 8; k++) {
            float a[8], b[8];
            #pragma unroll
            for (int i = 0; i < 8; i++) a[i] = As[k][ty * 8 + i];
            #pragma unroll
            for (int j = 0; j < 8; j++) b[j] = Bs[k][tx * 8 + j];
            #pragma unroll
            for (int i = 0; i < 8; i++)
                #pragma unroll
                for (int j = 0; j < 8; j++)
                    acc[i][j] += a[i] * b[j];
        }
        __syncthreads();
    }

    #pragma unroll
    for (int i = 0; i < 8; i++) {
        int r = row0 + ty * 8 + i;
        if (r < cnt) {
            int   tok = g_tok[e][r];
            float wgt = g_wgt[e][r];
            float* yp = y + (size_t)tok * DIM + col0 + tx * 8;
            #pragma unroll
            for (int j = 0; j < 8; j++) {
                int c = col0 + tx * 8 + j;
                atomicAdd(&yp[j], (acc[i][j] + b3[e * DIM + c]) * wgt);
            }
        }
    }
}

// ---------------- launch ----------------
extern "C" void kernel_launch(void* const* d_in, const int* in_sizes, int n_in,
                              void* d_out, int out_size) {
    const float* x  = (const float*)d_in[0];
    const float* gw = (const float*)d_in[1];
    const float* rs = (const float*)d_in[2];
    const float* w1 = (const float*)d_in[3];
    const float* b1 = (const float*)d_in[4];
    const float* w2 = (const float*)d_in[5];
    const float* b2 = (const float*)d_in[6];
    const float* w3 = (const float*)d_in[7];
    const float* b3 = (const float*)d_in[8];
    float* y = (float*)d_out;

    init_kernel<<<256, 256>>>(y, out_size);
    router_kernel<<<N_TOK / 8, 256>>>(x, gw, rs);
    scan_kernel<<<1, 32>>>();
    gemm_h_kernel<<<dim3(HID / 128, N_TOK / 128, NEXP), 256>>>(x, w1, b1, w2, b2);
    gemm_o_kernel<<<dim3(DIM / 128, N_TOK / 128, NEXP), 256>>>(w3, b3, y);
}